// round 10
// baseline (speedup 1.0000x reference)
#include <cuda_runtime.h>
#include <cooperative_groups.h>
namespace cg = cooperative_groups;

#define SEQ   2048
#define INDIM 256
#define HID   256
#define G3    768

// Precomputed input projection gx[b][t][768] (includes bx). ~805 MB scratch.
__device__ float g_gx[(size_t)128 * SEQ * G3];

// ---- f32x2 packed helpers (SASS FFMA2 path, PTX-only) ----------------------
static __device__ __forceinline__ unsigned long long dup2(float a) {
    unsigned long long r;
    asm("mov.b64 %0, {%1, %1};" : "=l"(r) : "f"(a));
    return r;
}
static __device__ __forceinline__ void fma2(unsigned long long& d,
                                            unsigned long long a,
                                            unsigned long long b) {
    asm("fma.rn.f32x2 %0, %1, %2, %0;" : "+l"(d) : "l"(a), "l"(b));
}
static __device__ __forceinline__ float2 unp2(unsigned long long v) {
    float2 r;
    asm("mov.b64 {%0, %1}, %2;" : "=f"(r.x), "=f"(r.y) : "l"(v));
    return r;
}
static __device__ __forceinline__ unsigned smem_u32(const void* p) {
    return (unsigned)__cvta_generic_to_shared(p);
}
static __device__ __forceinline__ void cp_async4(unsigned dst, const void* src) {
    asm volatile("cp.async.ca.shared.global [%0], [%1], 4;" :: "r"(dst), "l"(src));
}
static __device__ __forceinline__ void cp_commit() {
    asm volatile("cp.async.commit_group;" ::: "memory");
}
template <int N>
static __device__ __forceinline__ void cp_wait() {
    asm volatile("cp.async.wait_group %0;" :: "n"(N) : "memory");
}

// ---------------------------------------------------------------------------
// Phase 1 v2: gx = x @ Wx^T + bx.  (unchanged from round 8 — known good)
// ---------------------------------------------------------------------------
#define GXP 132
#define GX_BUF (32 * GXP)
#define GX_SMEM (4 * GX_BUF * 4)      // 67584 B

__global__ void __launch_bounds__(256, 2)
gx_gemm(const float* __restrict__ x, const float* __restrict__ Wx,
        const float* __restrict__ bx) {
    extern __shared__ float sm[];
    float* As = sm;
    float* Bs = sm + 2 * GX_BUF;

    const int bid = blockIdx.x;
    const int mt = bid / 6;
    const int nt = bid % 6;
    const long m0 = (long)mt * 128;
    const int  n0 = nt * 128;
    const int tid = threadIdx.x;
    const int wid = tid >> 5;
    const int lane = tid & 31;

    const unsigned sA = smem_u32(As);
    const unsigned sB = smem_u32(Bs);

    auto load_chunk = [&](int c) {
        const int buf = c & 1;
        const int k0 = c * 32;
        const unsigned dA = sA + (buf * GX_BUF + lane * GXP) * 4;
        const unsigned dB = sB + (buf * GX_BUF + lane * GXP) * 4;
        const float* gA = x + (m0 + wid * 16) * INDIM + k0 + lane;
        const float* gB = Wx + (long)(n0 + wid * 16) * INDIM + k0 + lane;
#pragma unroll
        for (int i = 0; i < 16; i++) {
            int row = wid * 16 + i;
            cp_async4(dA + row * 4, gA + i * INDIM);
            cp_async4(dB + row * 4, gB + i * INDIM);
        }
        cp_commit();
    };

    load_chunk(0);
    load_chunk(1);

    const int tm = (tid & 15) * 8;
    const int tn = (tid >> 4) * 8;

    unsigned long long acc[4][8];
#pragma unroll
    for (int i = 0; i < 4; i++)
#pragma unroll
        for (int j = 0; j < 8; j++) acc[i][j] = 0ull;

#pragma unroll 1
    for (int c = 0; c < 8; c++) {
        if (c < 6) cp_wait<1>(); else cp_wait<0>();
        __syncthreads();

        const float* ab = As + (c & 1) * GX_BUF;
        const float* bb = Bs + (c & 1) * GX_BUF;
#pragma unroll 8
        for (int k = 0; k < 32; k++) {
            ulonglong2 a0 = *(const ulonglong2*)(ab + k * GXP + tm);
            ulonglong2 a1 = *(const ulonglong2*)(ab + k * GXP + tm + 4);
            float4 b0 = *(const float4*)(bb + k * GXP + tn);
            float4 b1 = *(const float4*)(bb + k * GXP + tn + 4);
            unsigned long long am[4] = {a0.x, a0.y, a1.x, a1.y};
            float bn[8] = {b0.x, b0.y, b0.z, b0.w, b1.x, b1.y, b1.z, b1.w};
#pragma unroll
            for (int j = 0; j < 8; j++) {
                unsigned long long bd = dup2(bn[j]);
#pragma unroll
                for (int i = 0; i < 4; i++)
                    fma2(acc[i][j], am[i], bd);
            }
        }
        __syncthreads();
        if (c + 2 < 8) load_chunk(c + 2);
    }

    float bn[8];
#pragma unroll
    for (int j = 0; j < 8; j++) bn[j] = bx[n0 + tn + j];
#pragma unroll
    for (int i = 0; i < 4; i++) {
        float lo[8], hi[8];
#pragma unroll
        for (int j = 0; j < 8; j++) {
            float2 f = unp2(acc[i][j]);
            lo[j] = f.x + bn[j];
            hi[j] = f.y + bn[j];
        }
        float* r0 = &g_gx[(m0 + tm + 2 * i) * G3 + n0 + tn];
        float* r1 = r0 + G3;
        *(float4*)(r0)     = make_float4(lo[0], lo[1], lo[2], lo[3]);
        *(float4*)(r0 + 4) = make_float4(lo[4], lo[5], lo[6], lo[7]);
        *(float4*)(r1)     = make_float4(hi[0], hi[1], hi[2], hi[3]);
        *(float4*)(r1 + 4) = make_float4(hi[4], hi[5], hi[6], hi[7]);
    }
}

// ---------------------------------------------------------------------------
// Phase 2: persistent recurrence v8 — deeper row amortization of h.
// 32 clusters x 4 CTAs, 256 threads. CTA owns 64 units -> 192 gate rows.
// Thread (g = tid>>3 in 0..31, q = tid&7): rows 6g..6g+5, k-slabs
// k=(8s+q)*4 (s<8), all 4 batches, k-pair-packed f32x2 (24 accumulators).
// Phases/step: w 1536 (floor) + h 1024 + parts ~192 + gate ~192 = ~2944.
// Gate phase uses all 256 threads exactly (64 units x 4 batches).
// ---------------------------------------------------------------------------
#define CLUSTER 4
#define UB    64
#define ROWS  192
#define NTHR  256
#define HPAD  256
#define PBLK  772

#define OFF_HB (ROWS * 256)                 // 49152: ws = 192x256
#define OFF_P  (OFF_HB + 2 * 4 * HPAD)      // 51200: hbuf = 2x4x256
#define REC_SMEM ((OFF_P + 8 * PBLK) * 4)   // 229504 B

__global__ void __launch_bounds__(NTHR, 1) __cluster_dims__(CLUSTER, 1, 1)
gru_rec(const float* __restrict__ Wh, const float* __restrict__ bh,
        const float* __restrict__ Wfc, const float* __restrict__ bfc,
        float* __restrict__ out) {
    extern __shared__ float sm[];
    float* ws   = sm;            // ws[r][256], r<192 local gate row
    float* hbuf = sm + OFF_HB;   // hbuf[buf*4 + b][256]
    float* part = sm + OFF_P;    // part[q][b*192 + row], q-stride PBLK

    cg::cluster_group cl = cg::this_cluster();
    const int rank = (int)cl.block_rank();
    const int clid = (int)blockIdx.x / CLUSTER;
    const int tid  = threadIdx.x;
    const int U0   = rank * UB;
    const int B0   = clid * 4;

    // Load Wh slice: local row r = gate*64+u -> global row gate*256 + U0 + u
    for (int e4 = tid; e4 < ROWS * (HID / 4); e4 += NTHR) {
        int r = e4 >> 6;
        int k = (e4 & 63) << 2;
        int grow = (r >> 6) * HID + U0 + (r & 63);
        *(float4*)&ws[r * 256 + k] = *(const float4*)&Wh[(long)grow * HID + k];
    }
    for (int i = tid; i < 2 * 4 * HPAD; i += NTHR)
        hbuf[i] = 0.0f;
    __syncthreads();

    const int g = tid >> 3;             // row-group 0..31 (rows 6g..6g+5)
    const int q = tid & 7;              // k-chunk
    const float* wp = ws + g * 6 * 256;

    const int gu = tid & 63;            // gate unit
    const int gb = tid >> 6;            // gate batch (0..3) — exactly 256 thr
    const float bhr = bh[U0 + gu];
    const float bhz = bh[256 + U0 + gu];
    const float bhn = bh[512 + U0 + gu];
    float hprev = 0.0f;

    float* peer_hb[CLUSTER];
#pragma unroll
    for (int rr = 0; rr < CLUSTER; rr++)
        peer_hb[rr] = (float*)cl.map_shared_rank(hbuf, rr);

    const float* gxp = g_gx + ((long)(B0 + gb) * SEQ) * G3 + (U0 + gu);

    cl.sync();   // zeroed hbufs visible before any peer DSMEM write

    for (int t = 0; t < SEQ; t++) {
        const int cur = t & 1;
        const int nxt = cur ^ 1;

        // gx prefetch for step t (hidden under the dot)
        const float* gp = gxp + (long)t * G3;
        float gcr = gp[0], gcz = gp[256], gcn = gp[512];

        // Dot: 6 rows x 32 k x 4 batches, k-pair-packed. acc[b*6 + r].
        const float* hb = hbuf + cur * 4 * HPAD;
        unsigned long long acc[24];
#pragma unroll
        for (int i = 0; i < 24; i++) acc[i] = 0ull;

#pragma unroll
        for (int s = 0; s < 8; s++) {
            const int kb = (s * 8 + q) * 4;
            ulonglong2 w0 = *(const ulonglong2*)(wp + 0 * 256 + kb);
            ulonglong2 w1 = *(const ulonglong2*)(wp + 1 * 256 + kb);
            ulonglong2 w2 = *(const ulonglong2*)(wp + 2 * 256 + kb);
            ulonglong2 w3 = *(const ulonglong2*)(wp + 3 * 256 + kb);
            ulonglong2 w4 = *(const ulonglong2*)(wp + 4 * 256 + kb);
            ulonglong2 w5 = *(const ulonglong2*)(wp + 5 * 256 + kb);
            ulonglong2 h0 = *(const ulonglong2*)(hb + 0 * HPAD + kb);
            ulonglong2 h1 = *(const ulonglong2*)(hb + 1 * HPAD + kb);
            ulonglong2 h2 = *(const ulonglong2*)(hb + 2 * HPAD + kb);
            ulonglong2 h3 = *(const ulonglong2*)(hb + 3 * HPAD + kb);
            fma2(acc[0],  w0.x, h0.x); fma2(acc[0],  w0.y, h0.y);
            fma2(acc[1],  w1.x, h0.x); fma2(acc[1],  w1.y, h0.y);
            fma2(acc[2],  w2.x, h0.x); fma2(acc[2],  w2.y, h0.y);
            fma2(acc[3],  w3.x, h0.x); fma2(acc[3],  w3.y, h0.y);
            fma2(acc[4],  w4.x, h0.x); fma2(acc[4],  w4.y, h0.y);
            fma2(acc[5],  w5.x, h0.x); fma2(acc[5],  w5.y, h0.y);
            fma2(acc[6],  w0.x, h1.x); fma2(acc[6],  w0.y, h1.y);
            fma2(acc[7],  w1.x, h1.x); fma2(acc[7],  w1.y, h1.y);
            fma2(acc[8],  w2.x, h1.x); fma2(acc[8],  w2.y, h1.y);
            fma2(acc[9],  w3.x, h1.x); fma2(acc[9],  w3.y, h1.y);
            fma2(acc[10], w4.x, h1.x); fma2(acc[10], w4.y, h1.y);
            fma2(acc[11], w5.x, h1.x); fma2(acc[11], w5.y, h1.y);
            fma2(acc[12], w0.x, h2.x); fma2(acc[12], w0.y, h2.y);
            fma2(acc[13], w1.x, h2.x); fma2(acc[13], w1.y, h2.y);
            fma2(acc[14], w2.x, h2.x); fma2(acc[14], w2.y, h2.y);
            fma2(acc[15], w3.x, h2.x); fma2(acc[15], w3.y, h2.y);
            fma2(acc[16], w4.x, h2.x); fma2(acc[16], w4.y, h2.y);
            fma2(acc[17], w5.x, h2.x); fma2(acc[17], w5.y, h2.y);
            fma2(acc[18], w0.x, h3.x); fma2(acc[18], w0.y, h3.y);
            fma2(acc[19], w1.x, h3.x); fma2(acc[19], w1.y, h3.y);
            fma2(acc[20], w2.x, h3.x); fma2(acc[20], w2.y, h3.y);
            fma2(acc[21], w3.x, h3.x); fma2(acc[21], w3.y, h3.y);
            fma2(acc[22], w4.x, h3.x); fma2(acc[22], w4.y, h3.y);
            fma2(acc[23], w5.x, h3.x); fma2(acc[23], w5.y, h3.y);
        }

        // Horizontal k-pair sums; 3x STS.64 per batch (6 rows, 8B aligned)
        {
            float* pq = part + q * PBLK + g * 6;
#pragma unroll
            for (int b = 0; b < 4; b++) {
                float2 f0 = unp2(acc[b * 6 + 0]);
                float2 f1 = unp2(acc[b * 6 + 1]);
                float2 f2 = unp2(acc[b * 6 + 2]);
                float2 f3 = unp2(acc[b * 6 + 3]);
                float2 f4 = unp2(acc[b * 6 + 4]);
                float2 f5 = unp2(acc[b * 6 + 5]);
                float* dst = pq + b * 192;
                *(float2*)(dst + 0) = make_float2(f0.x + f0.y, f1.x + f1.y);
                *(float2*)(dst + 2) = make_float2(f2.x + f2.y, f3.x + f3.y);
                *(float2*)(dst + 4) = make_float2(f4.x + f4.y, f5.x + f5.y);
            }
        }
        __syncthreads();

        // Gate phase: all 256 threads, one (unit,batch) each
        {
            float sr = bhr, sz = bhz, sn = bhn;
#pragma unroll
            for (int qq = 0; qq < 8; qq++) {
                const float* pq = part + qq * PBLK + gb * 192;
                sr += pq[gu];
                sz += pq[64 + gu];
                sn += pq[128 + gu];
            }
            float rg = __fdividef(1.0f, 1.0f + __expf(-(gcr + sr)));
            float zg = __fdividef(1.0f, 1.0f + __expf(-(gcz + sz)));
            float na = gcn + rg * sn;
            float ng = 2.0f * __fdividef(1.0f, 1.0f + __expf(-2.0f * na)) - 1.0f;
            float hnew = ng + zg * (hprev - ng);
            hprev = hnew;
            const int off = (nxt * 4 + gb) * HPAD + (U0 + gu);
#pragma unroll
            for (int rr = 0; rr < CLUSTER; rr++)
                peer_hb[rr][off] = hnew;
        }
        cl.sync();   // h(t+1) complete in every CTA
    }

    // Final h lives in hbuf[0] (t=2047: nxt=0). Rank 0 emits out[b][2].
    if (rank == 0) {
        const int w = tid >> 5, lane = tid & 31;
        if (w < 8) {
            const int bb = w >> 1, o = w & 1;
            const float* hf = hbuf + bb * HPAD;
            float s = 0.f;
            for (int k = lane; k < HID; k += 32)
                s += hf[k] * __ldg(&Wfc[o * HID + k]);
#pragma unroll
            for (int d = 16; d > 0; d >>= 1)
                s += __shfl_xor_sync(0xFFFFFFFFu, s, d);
            if (lane == 0)
                out[(B0 + bb) * 2 + o] = s + bfc[o];
        }
    }
}

// ---------------------------------------------------------------------------
extern "C" void kernel_launch(void* const* d_in, const int* in_sizes, int n_in,
                              void* d_out, int out_size) {
    const float* x   = (const float*)d_in[0];
    const float* Wx  = (const float*)d_in[1];
    const float* bx  = (const float*)d_in[2];
    const float* Wh  = (const float*)d_in[3];
    const float* bh  = (const float*)d_in[4];
    const float* Wfc = (const float*)d_in[5];
    const float* bfc = (const float*)d_in[6];
    float* out = (float*)d_out;

    cudaFuncSetAttribute(gx_gemm, cudaFuncAttributeMaxDynamicSharedMemorySize, GX_SMEM);
    cudaFuncSetAttribute(gru_rec, cudaFuncAttributeMaxDynamicSharedMemorySize, REC_SMEM);

    const int mtiles = (128 * SEQ) / 128;    // 2048
    const int ntiles = G3 / 128;             // 6
    gx_gemm<<<mtiles * ntiles, 256, GX_SMEM>>>(x, Wx, bx);
    gru_rec<<<32 * CLUSTER, NTHR, REC_SMEM>>>(Wh, bh, Wfc, bfc, out);
}

// round 11
// speedup vs baseline: 1.1325x; 1.1325x over previous
#include <cuda_runtime.h>
#include <cooperative_groups.h>
namespace cg = cooperative_groups;

#define SEQ   2048
#define INDIM 256
#define HID   256
#define G3    768

// Precomputed input projection gx[b][t][768] (includes bx). ~805 MB scratch.
__device__ float g_gx[(size_t)128 * SEQ * G3];

// ---- f32x2 packed helpers (SASS FFMA2 path, PTX-only) ----------------------
static __device__ __forceinline__ unsigned long long dup2(float a) {
    unsigned long long r;
    asm("mov.b64 %0, {%1, %1};" : "=l"(r) : "f"(a));
    return r;
}
static __device__ __forceinline__ void fma2(unsigned long long& d,
                                            unsigned long long a,
                                            unsigned long long b) {
    asm("fma.rn.f32x2 %0, %1, %2, %0;" : "+l"(d) : "l"(a), "l"(b));
}
static __device__ __forceinline__ float2 unp2(unsigned long long v) {
    float2 r;
    asm("mov.b64 {%0, %1}, %2;" : "=f"(r.x), "=f"(r.y) : "l"(v));
    return r;
}
static __device__ __forceinline__ unsigned smem_u32(const void* p) {
    return (unsigned)__cvta_generic_to_shared(p);
}
static __device__ __forceinline__ void cp_async4(unsigned dst, const void* src) {
    asm volatile("cp.async.ca.shared.global [%0], [%1], 4;" :: "r"(dst), "l"(src));
}
static __device__ __forceinline__ void cp_commit() {
    asm volatile("cp.async.commit_group;" ::: "memory");
}
template <int N>
static __device__ __forceinline__ void cp_wait() {
    asm volatile("cp.async.wait_group %0;" :: "n"(N) : "memory");
}

// ---------------------------------------------------------------------------
// Phase 1 v2: gx = x @ Wx^T + bx.  (unchanged from round 8 — known good)
// ---------------------------------------------------------------------------
#define GXP 132
#define GX_BUF (32 * GXP)
#define GX_SMEM (4 * GX_BUF * 4)      // 67584 B

__global__ void __launch_bounds__(256, 2)
gx_gemm(const float* __restrict__ x, const float* __restrict__ Wx,
        const float* __restrict__ bx) {
    extern __shared__ float sm[];
    float* As = sm;
    float* Bs = sm + 2 * GX_BUF;

    const int bid = blockIdx.x;
    const int mt = bid / 6;
    const int nt = bid % 6;
    const long m0 = (long)mt * 128;
    const int  n0 = nt * 128;
    const int tid = threadIdx.x;
    const int wid = tid >> 5;
    const int lane = tid & 31;

    const unsigned sA = smem_u32(As);
    const unsigned sB = smem_u32(Bs);

    auto load_chunk = [&](int c) {
        const int buf = c & 1;
        const int k0 = c * 32;
        const unsigned dA = sA + (buf * GX_BUF + lane * GXP) * 4;
        const unsigned dB = sB + (buf * GX_BUF + lane * GXP) * 4;
        const float* gA = x + (m0 + wid * 16) * INDIM + k0 + lane;
        const float* gB = Wx + (long)(n0 + wid * 16) * INDIM + k0 + lane;
#pragma unroll
        for (int i = 0; i < 16; i++) {
            int row = wid * 16 + i;
            cp_async4(dA + row * 4, gA + i * INDIM);
            cp_async4(dB + row * 4, gB + i * INDIM);
        }
        cp_commit();
    };

    load_chunk(0);
    load_chunk(1);

    const int tm = (tid & 15) * 8;
    const int tn = (tid >> 4) * 8;

    unsigned long long acc[4][8];
#pragma unroll
    for (int i = 0; i < 4; i++)
#pragma unroll
        for (int j = 0; j < 8; j++) acc[i][j] = 0ull;

#pragma unroll 1
    for (int c = 0; c < 8; c++) {
        if (c < 6) cp_wait<1>(); else cp_wait<0>();
        __syncthreads();

        const float* ab = As + (c & 1) * GX_BUF;
        const float* bb = Bs + (c & 1) * GX_BUF;
#pragma unroll 8
        for (int k = 0; k < 32; k++) {
            ulonglong2 a0 = *(const ulonglong2*)(ab + k * GXP + tm);
            ulonglong2 a1 = *(const ulonglong2*)(ab + k * GXP + tm + 4);
            float4 b0 = *(const float4*)(bb + k * GXP + tn);
            float4 b1 = *(const float4*)(bb + k * GXP + tn + 4);
            unsigned long long am[4] = {a0.x, a0.y, a1.x, a1.y};
            float bn[8] = {b0.x, b0.y, b0.z, b0.w, b1.x, b1.y, b1.z, b1.w};
#pragma unroll
            for (int j = 0; j < 8; j++) {
                unsigned long long bd = dup2(bn[j]);
#pragma unroll
                for (int i = 0; i < 4; i++)
                    fma2(acc[i][j], am[i], bd);
            }
        }
        __syncthreads();
        if (c + 2 < 8) load_chunk(c + 2);
    }

    float bn[8];
#pragma unroll
    for (int j = 0; j < 8; j++) bn[j] = bx[n0 + tn + j];
#pragma unroll
    for (int i = 0; i < 4; i++) {
        float lo[8], hi[8];
#pragma unroll
        for (int j = 0; j < 8; j++) {
            float2 f = unp2(acc[i][j]);
            lo[j] = f.x + bn[j];
            hi[j] = f.y + bn[j];
        }
        float* r0 = &g_gx[(m0 + tm + 2 * i) * G3 + n0 + tn];
        float* r1 = r0 + G3;
        *(float4*)(r0)     = make_float4(lo[0], lo[1], lo[2], lo[3]);
        *(float4*)(r0 + 4) = make_float4(lo[4], lo[5], lo[6], lo[7]);
        *(float4*)(r1)     = make_float4(hi[0], hi[1], hi[2], hi[3]);
        *(float4*)(r1 + 4) = make_float4(hi[4], hi[5], hi[6], hi[7]);
    }
}

// ---------------------------------------------------------------------------
// Phase 2: persistent recurrence v9 — v7 layout + 2 rows of w in registers.
// 32 clusters x 4 CTAs, 384 threads. CTA owns 64 units -> 192 gate rows.
// Thread (g = tid>>3, q = tid&7): rows 4g..4g+3, k-slabs k=(8s+q)*4 (s<8),
// all 4 batches, k-pair-packed f32x2 (16 accumulators).
// Rows 4g, 4g+1 weights live in REGISTERS (64 regs) -> w phases 1536 -> 768.
// Phases/step: w 768 + h 1536 + parts 192 + gate 192 = ~2688 (+~400 sync).
// ---------------------------------------------------------------------------
#define CLUSTER 4
#define UB    64
#define ROWS  192
#define NTHR  384
#define HPAD  256
#define PBLK  772

#define OFF_HB (ROWS * 256)                 // 49152: ws = 192x256
#define OFF_P  (OFF_HB + 2 * 4 * HPAD)      // 51200: hbuf = 2x4x256
#define REC_SMEM ((OFF_P + 8 * PBLK) * 4)   // 229504 B

__global__ void __launch_bounds__(NTHR, 1) __cluster_dims__(CLUSTER, 1, 1)
gru_rec(const float* __restrict__ Wh, const float* __restrict__ bh,
        const float* __restrict__ Wfc, const float* __restrict__ bfc,
        float* __restrict__ out) {
    extern __shared__ float sm[];
    float* ws   = sm;            // ws[r][256], r<192 local gate row
    float* hbuf = sm + OFF_HB;   // hbuf[buf*4 + b][256]
    float* part = sm + OFF_P;    // part[q][b*192 + row], q-stride PBLK

    cg::cluster_group cl = cg::this_cluster();
    const int rank = (int)cl.block_rank();
    const int clid = (int)blockIdx.x / CLUSTER;
    const int tid  = threadIdx.x;
    const int U0   = rank * UB;
    const int B0   = clid * 4;

    // Load Wh slice: local row r = gate*64+u -> global row gate*256 + U0 + u
    for (int e4 = tid; e4 < ROWS * (HID / 4); e4 += NTHR) {
        int r = e4 >> 6;
        int k = (e4 & 63) << 2;
        int grow = (r >> 6) * HID + U0 + (r & 63);
        *(float4*)&ws[r * 256 + k] = *(const float4*)&Wh[(long)grow * HID + k];
    }
    for (int i = tid; i < 2 * 4 * HPAD; i += NTHR)
        hbuf[i] = 0.0f;
    __syncthreads();

    const int g = tid >> 3;             // row-group 0..47 (rows 4g..4g+3)
    const int q = tid & 7;              // k-chunk
    const float* wp = ws + (g << 2) * 256;

    // Rows 4g, 4g+1 weights -> registers (this thread's 8 slabs x 4 floats)
    unsigned long long wa0[16], wa1[16];
#pragma unroll
    for (int s = 0; s < 8; s++) {
        const int kb = (s * 8 + q) * 4;
        ulonglong2 t0 = *(const ulonglong2*)(wp + 0 * 256 + kb);
        ulonglong2 t1 = *(const ulonglong2*)(wp + 1 * 256 + kb);
        wa0[2 * s] = t0.x; wa0[2 * s + 1] = t0.y;
        wa1[2 * s] = t1.x; wa1[2 * s + 1] = t1.y;
    }

    const int gu = tid & 63;            // gate-phase unit  (tid < 256)
    const int gb = (tid >> 6) & 3;      // gate-phase batch (tid < 256)
    const bool is_gate = (tid < 256);
    const float bhr = is_gate ? bh[U0 + gu]       : 0.f;
    const float bhz = is_gate ? bh[256 + U0 + gu] : 0.f;
    const float bhn = is_gate ? bh[512 + U0 + gu] : 0.f;
    float hprev = 0.0f;

    float* peer_hb[CLUSTER];
#pragma unroll
    for (int rr = 0; rr < CLUSTER; rr++)
        peer_hb[rr] = (float*)cl.map_shared_rank(hbuf, rr);

    const float* gxp = g_gx + ((long)(B0 + gb) * SEQ) * G3 + (U0 + gu);

    cl.sync();   // zeroed hbufs visible before any peer DSMEM write

    for (int t = 0; t < SEQ; t++) {
        const int cur = t & 1;
        const int nxt = cur ^ 1;

        // gx prefetch for step t (hidden under the dot)
        float gcr = 0.f, gcz = 0.f, gcn = 0.f;
        if (is_gate) {
            const float* gp = gxp + (long)t * G3;
            gcr = gp[0]; gcz = gp[256]; gcn = gp[512];
        }

        // Dot: 4 rows x 32 k x 4 batches; rows 0-1 w from regs, 2-3 from smem.
        const float* hb = hbuf + cur * 4 * HPAD;
        unsigned long long acc[16];
#pragma unroll
        for (int i = 0; i < 16; i++) acc[i] = 0ull;

#pragma unroll
        for (int s = 0; s < 8; s++) {
            const int kb = (s * 8 + q) * 4;
            const unsigned long long w0x = wa0[2 * s], w0y = wa0[2 * s + 1];
            const unsigned long long w1x = wa1[2 * s], w1y = wa1[2 * s + 1];
            ulonglong2 w2 = *(const ulonglong2*)(wp + 2 * 256 + kb);
            ulonglong2 w3 = *(const ulonglong2*)(wp + 3 * 256 + kb);
            ulonglong2 h0 = *(const ulonglong2*)(hb + 0 * HPAD + kb);
            ulonglong2 h1 = *(const ulonglong2*)(hb + 1 * HPAD + kb);
            ulonglong2 h2 = *(const ulonglong2*)(hb + 2 * HPAD + kb);
            ulonglong2 h3 = *(const ulonglong2*)(hb + 3 * HPAD + kb);
            fma2(acc[0],  w0x, h0.x); fma2(acc[0],  w0y, h0.y);
            fma2(acc[1],  w1x, h0.x); fma2(acc[1],  w1y, h0.y);
            fma2(acc[2],  w2.x, h0.x); fma2(acc[2],  w2.y, h0.y);
            fma2(acc[3],  w3.x, h0.x); fma2(acc[3],  w3.y, h0.y);
            fma2(acc[4],  w0x, h1.x); fma2(acc[4],  w0y, h1.y);
            fma2(acc[5],  w1x, h1.x); fma2(acc[5],  w1y, h1.y);
            fma2(acc[6],  w2.x, h1.x); fma2(acc[6],  w2.y, h1.y);
            fma2(acc[7],  w3.x, h1.x); fma2(acc[7],  w3.y, h1.y);
            fma2(acc[8],  w0x, h2.x); fma2(acc[8],  w0y, h2.y);
            fma2(acc[9],  w1x, h2.x); fma2(acc[9],  w1y, h2.y);
            fma2(acc[10], w2.x, h2.x); fma2(acc[10], w2.y, h2.y);
            fma2(acc[11], w3.x, h2.x); fma2(acc[11], w3.y, h2.y);
            fma2(acc[12], w0x, h3.x); fma2(acc[12], w0y, h3.y);
            fma2(acc[13], w1x, h3.x); fma2(acc[13], w1y, h3.y);
            fma2(acc[14], w2.x, h3.x); fma2(acc[14], w2.y, h3.y);
            fma2(acc[15], w3.x, h3.x); fma2(acc[15], w3.y, h3.y);
        }

        // Horizontal k-pair sum, store 4 rows per batch as one STS.128
        {
            float* pq = part + q * PBLK + (g << 2);
#pragma unroll
            for (int b = 0; b < 4; b++) {
                float2 f0 = unp2(acc[b * 4 + 0]);
                float2 f1 = unp2(acc[b * 4 + 1]);
                float2 f2 = unp2(acc[b * 4 + 2]);
                float2 f3 = unp2(acc[b * 4 + 3]);
                float4 o;
                o.x = f0.x + f0.y; o.y = f1.x + f1.y;
                o.z = f2.x + f2.y; o.w = f3.x + f3.y;
                *(float4*)(pq + b * 192) = o;
            }
        }
        __syncthreads();

        if (is_gate) {
            float sr = bhr, sz = bhz, sn = bhn;
#pragma unroll
            for (int qq = 0; qq < 8; qq++) {
                const float* pq = part + qq * PBLK + gb * 192;
                sr += pq[gu];
                sz += pq[64 + gu];
                sn += pq[128 + gu];
            }
            float rg = __fdividef(1.0f, 1.0f + __expf(-(gcr + sr)));
            float zg = __fdividef(1.0f, 1.0f + __expf(-(gcz + sz)));
            float na = gcn + rg * sn;
            float ng = 2.0f * __fdividef(1.0f, 1.0f + __expf(-2.0f * na)) - 1.0f;
            float hnew = ng + zg * (hprev - ng);
            hprev = hnew;
            const int off = (nxt * 4 + gb) * HPAD + (U0 + gu);
#pragma unroll
            for (int rr = 0; rr < CLUSTER; rr++)
                peer_hb[rr][off] = hnew;
        }
        cl.sync();   // h(t+1) complete in every CTA
    }

    // Final h lives in hbuf[0] (t=2047: nxt=0). Rank 0 emits out[b][2].
    if (rank == 0) {
        const int w = tid >> 5, lane = tid & 31;
        if (w < 8) {
            const int bb = w >> 1, o = w & 1;
            const float* hf = hbuf + bb * HPAD;
            float s = 0.f;
            for (int k = lane; k < HID; k += 32)
                s += hf[k] * __ldg(&Wfc[o * HID + k]);
#pragma unroll
            for (int d = 16; d > 0; d >>= 1)
                s += __shfl_xor_sync(0xFFFFFFFFu, s, d);
            if (lane == 0)
                out[(B0 + bb) * 2 + o] = s + bfc[o];
        }
    }
}

// ---------------------------------------------------------------------------
extern "C" void kernel_launch(void* const* d_in, const int* in_sizes, int n_in,
                              void* d_out, int out_size) {
    const float* x   = (const float*)d_in[0];
    const float* Wx  = (const float*)d_in[1];
    const float* bx  = (const float*)d_in[2];
    const float* Wh  = (const float*)d_in[3];
    const float* bh  = (const float*)d_in[4];
    const float* Wfc = (const float*)d_in[5];
    const float* bfc = (const float*)d_in[6];
    float* out = (float*)d_out;

    cudaFuncSetAttribute(gx_gemm, cudaFuncAttributeMaxDynamicSharedMemorySize, GX_SMEM);
    cudaFuncSetAttribute(gru_rec, cudaFuncAttributeMaxDynamicSharedMemorySize, REC_SMEM);

    const int mtiles = (128 * SEQ) / 128;    // 2048
    const int ntiles = G3 / 128;             // 6
    gx_gemm<<<mtiles * ntiles, 256, GX_SMEM>>>(x, Wx, bx);
    gru_rec<<<32 * CLUSTER, NTHR, REC_SMEM>>>(Wh, bh, Wfc, bfc, out);
}